// round 4
// baseline (speedup 1.0000x reference)
#include <cuda_runtime.h>
#include <math.h>

// Problem constants (fixed shapes from reference setup_inputs)
#define T_STEPS 512
#define BATCH   128
#define MDIM    31
#define HID     512
#define EMB     256
#define SDIM    128
#define G3      (3*HID)          // 1536
#define TB      (T_STEPS*BATCH)  // 65536

#define SIGMA_MIN 0.01f
#define GAMMA     1.0f
#define LOG2PI    1.8378770664093453f

// Scratch (device globals: no allocations allowed)
__device__ float g_phi[TB*EMB];                 //  67 MB
__device__ float g_xg [(size_t)TB*G3];          // 402 MB
__device__ float g_hs [(size_t)TB*HID];         // 134 MB  (hs[t] = h_t; hs[0]=0)
__device__ float g_loss[TB];                    // per-(t,b) loss, t>=1 written

__device__ __forceinline__ float sigmoidf_(float v) {
    return 1.0f / (1.0f + expf(-v));
}

// ---------------------------------------------------------------------------
// Kernel 0: zero h_0
// ---------------------------------------------------------------------------
__global__ void zero_h0_kernel() {
    int i = blockIdx.x * blockDim.x + threadIdx.x;
    if (i < BATCH * HID) g_hs[i] = 0.0f;
}

// ---------------------------------------------------------------------------
// Kernel 1: phi = relu(x @ W_embed^T + b_embed)   [TB,31] -> [TB,256]
// 16 rows per CTA, W_embed staged in smem.
// ---------------------------------------------------------------------------
__global__ void phi_kernel(const float* __restrict__ x,
                           const float* __restrict__ W_embed,
                           const float* __restrict__ b_embed) {
    __shared__ float Ws[EMB * MDIM];   // 31.0 KB
    __shared__ float Xs[16 * MDIM];

    const int tid  = threadIdx.x;      // 256 threads
    const int row0 = blockIdx.x * 16;

    for (int i = tid; i < EMB * MDIM; i += 256) Ws[i] = W_embed[i];
    for (int i = tid; i < 16 * MDIM;  i += 256) Xs[i] = x[row0 * MDIM + i];
    __syncthreads();

    const int e = tid;                 // one output column per thread
    const float be = b_embed[e];
    #pragma unroll 4
    for (int r = 0; r < 16; ++r) {
        float acc = be;
        #pragma unroll
        for (int k = 0; k < MDIM; ++k)
            acc += Xs[r * MDIM + k] * Ws[e * MDIM + k];
        g_phi[(row0 + r) * EMB + e] = fmaxf(acc, 0.0f);
    }
}

// ---------------------------------------------------------------------------
// Kernel 2: x_gates = phi @ W_ih^T + b_ih   [TB,256] x [1536,256] -> [TB,1536]
// Classic smem-tiled GEMM: BM=64, BN=64, BK=16, 16x16 threads, 4x4 microtile.
// ---------------------------------------------------------------------------
__global__ void xg_kernel(const float* __restrict__ W_ih,
                          const float* __restrict__ b_ih) {
    __shared__ float As[64][17];
    __shared__ float Bs[64][17];

    const int tid = threadIdx.x;       // 256
    const int tx = tid & 15;
    const int ty = tid >> 4;
    const int n0 = blockIdx.x * 64;    // over G3 (24 tiles)
    const int m0 = blockIdx.y * 64;    // over TB (1024 tiles)

    float c[4][4];
    #pragma unroll
    for (int i = 0; i < 4; ++i)
        #pragma unroll
        for (int j = 0; j < 4; ++j) c[i][j] = 0.0f;

    const int lrow = tid >> 2;
    const int lcol = (tid & 3) * 4;

    for (int kc = 0; kc < EMB; kc += 16) {
        float4 av = *reinterpret_cast<const float4*>(&g_phi[(m0 + lrow) * EMB + kc + lcol]);
        float4 bv = *reinterpret_cast<const float4*>(&W_ih[(size_t)(n0 + lrow) * EMB + kc + lcol]);
        As[lrow][lcol+0] = av.x; As[lrow][lcol+1] = av.y;
        As[lrow][lcol+2] = av.z; As[lrow][lcol+3] = av.w;
        Bs[lrow][lcol+0] = bv.x; Bs[lrow][lcol+1] = bv.y;
        Bs[lrow][lcol+2] = bv.z; Bs[lrow][lcol+3] = bv.w;
        __syncthreads();

        #pragma unroll
        for (int k = 0; k < 16; ++k) {
            float a[4], b[4];
            #pragma unroll
            for (int i = 0; i < 4; ++i) a[i] = As[ty*4 + i][k];
            #pragma unroll
            for (int j = 0; j < 4; ++j) b[j] = Bs[tx*4 + j][k];
            #pragma unroll
            for (int i = 0; i < 4; ++i)
                #pragma unroll
                for (int j = 0; j < 4; ++j) c[i][j] += a[i] * b[j];
        }
        __syncthreads();
    }

    #pragma unroll
    for (int i = 0; i < 4; ++i) {
        const int m = m0 + ty*4 + i;
        const int n = n0 + tx*4;
        float4 v;
        v.x = c[i][0] + b_ih[n+0];
        v.y = c[i][1] + b_ih[n+1];
        v.z = c[i][2] + b_ih[n+2];
        v.w = c[i][3] + b_ih[n+3];
        *reinterpret_cast<float4*>(&g_xg[(size_t)m * G3 + n]) = v;
    }
}

// ---------------------------------------------------------------------------
// Kernel 3: one GRU step. Computes h_{t+1} = GRU(h_t, xg[t]) into g_hs[t+1].
// GEMM M=128(batch), N=512(j), K=512 with 3 gate accumulators, fused epilogue.
// BM=16, BN=32, BK=32. 256 threads: tx=j (32), ty=m-group (8), 2 m-rows each.
// Grid (16 n-tiles, 8 m-tiles) = 128 CTAs.
// ---------------------------------------------------------------------------
__global__ void gru_step_kernel(int t,
                                const float* __restrict__ W_hh,
                                const float* __restrict__ b_hh) {
    __shared__ float As[16][32];       // h_t tile (broadcast reads)
    __shared__ float Bs[3][32][33];    // W_hh tiles for r,z,n rows (padded)

    const int tid = threadIdx.x;       // 256
    const int tx  = tid & 31;          // j within tile
    const int ty  = tid >> 5;          // 0..7
    const int n0  = blockIdx.x * 32;
    const int m0  = blockIdx.y * 16;

    const float* __restrict__ hprev = g_hs + (size_t)t * BATCH * HID;
    float*       __restrict__ hnext = g_hs + (size_t)(t + 1) * BATCH * HID;
    const float* __restrict__ xg    = g_xg + (size_t)t * BATCH * G3;

    float acc[3][2] = {{0.f,0.f},{0.f,0.f},{0.f,0.f}};

    for (int kc = 0; kc < HID; kc += 32) {
        // load h tile: 16x32 = 512 floats
        for (int i = tid; i < 512; i += 256) {
            int r = i >> 5, k = i & 31;
            As[r][k] = hprev[(m0 + r) * HID + kc + k];
        }
        // load W tiles: 3x32x32 = 3072 floats
        for (int i = tid; i < 3072; i += 256) {
            int g = i >> 10, rem = i & 1023;
            int n = rem >> 5, k = rem & 31;
            Bs[g][n][k] = W_hh[(size_t)(g * HID + n0 + n) * HID + kc + k];
        }
        __syncthreads();

        #pragma unroll
        for (int k = 0; k < 32; ++k) {
            float b0 = Bs[0][tx][k];
            float b1 = Bs[1][tx][k];
            float b2 = Bs[2][tx][k];
            float a0 = As[ty*2 + 0][k];
            float a1 = As[ty*2 + 1][k];
            acc[0][0] += a0 * b0; acc[0][1] += a1 * b0;
            acc[1][0] += a0 * b1; acc[1][1] += a1 * b1;
            acc[2][0] += a0 * b2; acc[2][1] += a1 * b2;
        }
        __syncthreads();
    }

    const int j = n0 + tx;
    const float bhr = b_hh[j];
    const float bhz = b_hh[HID + j];
    const float bhn = b_hh[2*HID + j];

    #pragma unroll
    for (int i = 0; i < 2; ++i) {
        const int b = m0 + ty*2 + i;
        const float hr = acc[0][i] + bhr;
        const float hz = acc[1][i] + bhz;
        const float hn = acc[2][i] + bhn;
        const float xr = xg[(size_t)b * G3 + j];
        const float xz = xg[(size_t)b * G3 + HID + j];
        const float xn = xg[(size_t)b * G3 + 2*HID + j];
        const float r  = sigmoidf_(xr + hr);
        const float z  = sigmoidf_(xz + hz);
        const float nn = tanhf(xn + r * hn);
        const float hp = hprev[(size_t)b * HID + j];
        hnext[(size_t)b * HID + j] = (1.0f - z) * nn + z * hp;
    }
}

// ---------------------------------------------------------------------------
// Kernel 4: per-(t,b) loss for t>=1.
// he = relu(W_he @ hs + b_he); mu/lv heads; Gaussian marker LL; RMTPP time LL.
// 8 rows per CTA, 256 threads.
// ---------------------------------------------------------------------------
__global__ void loss_kernel(const float* __restrict__ x,
                            const float* __restrict__ tin,
                            const float* __restrict__ mask,
                            const float* __restrict__ W_he,
                            const float* __restrict__ b_he,
                            const float* __restrict__ W_mu,
                            const float* __restrict__ b_mu,
                            const float* __restrict__ W_lv,
                            const float* __restrict__ b_lv,
                            const float* __restrict__ h_inf,
                            const float* __restrict__ t_inf,
                            const float* __restrict__ b_int) {
    __shared__ float Hs[8][HID];       // 16 KB
    __shared__ float Ws[SDIM][17];     // W_he chunk (BK=16), padded
    __shared__ float He[8][SDIM];      // 4 KB
    __shared__ float red[8][32];       // marker terms

    const int tid    = threadIdx.x;    // 256
    const int r_base = BATCH + blockIdx.x * 8;   // rows for t>=1

    // Phase 1: stage hs rows
    for (int i = tid; i < 8 * HID; i += 256) {
        int rr = i >> 9, k = i & (HID - 1);
        Hs[rr][k] = g_hs[(size_t)(r_base + rr) * HID + k];
    }
    __syncthreads();

    // Phase 2: he GEMM (8 x 128, K=512), chunked W_he through smem
    const int s    = tid & 127;
    const int rgrp = tid >> 7;         // 0 or 1
    float acc[4] = {0.f, 0.f, 0.f, 0.f};

    for (int kc = 0; kc < HID; kc += 16) {
        for (int i = tid; i < SDIM * 16; i += 256) {
            int s2 = i >> 4, k = i & 15;
            Ws[s2][k] = W_he[(size_t)s2 * HID + kc + k];
        }
        __syncthreads();
        #pragma unroll
        for (int k = 0; k < 16; ++k) {
            float w = Ws[s][k];
            #pragma unroll
            for (int q = 0; q < 4; ++q)
                acc[q] += Hs[rgrp + 2*q][kc + k] * w;
        }
        __syncthreads();
    }
    {
        const float bs = b_he[s];
        #pragma unroll
        for (int q = 0; q < 4; ++q)
            He[rgrp + 2*q][s] = fmaxf(acc[q] + bs, 0.0f);
    }
    __syncthreads();

    // Phase 3: mu / logvar heads + per-dim marker terms
    if (tid < 8 * MDIM) {
        const int r = tid / MDIM;
        const int m = tid % MDIM;
        float mu = b_mu[m];
        float lv = b_lv[m];
        #pragma unroll 4
        for (int k = 0; k < SDIM; ++k) {
            const float he = He[r][k];
            mu += W_mu[m * SDIM + k] * he;
            lv += W_lv[m * SDIM + k] * he;
        }
        const float sigma = fmaxf(expf(0.5f * lv), SIGMA_MIN);
        const float xv = x[(size_t)(r_base + r) * MDIM + m];
        const float d = (xv - mu) / sigma;
        red[r][m] = -0.5f * d * d - logf(sigma) - 0.5f * LOG2PI;
    }
    __syncthreads();

    // Phase 4: per-row finalize (deterministic sequential reduction)
    if (tid < 8) {
        const int r = tid;
        float marker_ll = 0.0f;
        for (int m = 0; m < MDIM; ++m) marker_ll += red[r][m];

        float past = 0.0f;
        for (int k = 0; k < SDIM; ++k) past += He[r][k] * h_inf[k];

        const float ti = t_inf[0];
        const float bi = b_int[0];
        const float tg = tin[(size_t)(r_base + r) * 2 + 1];
        const float term1 = past + ti * tg + bi;
        const float time_ll = term1 + (expf(past + bi) - expf(term1)) / ti;

        const int row = r_base + r;
        g_loss[row] = (GAMMA * (-time_ll) + (-marker_ll)) * mask[row];
    }
}

// ---------------------------------------------------------------------------
// Kernel 5: deterministic final reduction (double accumulation)
// ---------------------------------------------------------------------------
__global__ void reduce_kernel(float* __restrict__ out) {
    __shared__ double sd[256];
    const int tid = threadIdx.x;
    double s = 0.0;
    for (int i = BATCH + tid; i < TB; i += 256) s += (double)g_loss[i];
    sd[tid] = s;
    __syncthreads();
    for (int off = 128; off > 0; off >>= 1) {
        if (tid < off) sd[tid] += sd[tid + off];
        __syncthreads();
    }
    if (tid == 0) out[0] = (float)sd[0];
}

// ---------------------------------------------------------------------------
extern "C" void kernel_launch(void* const* d_in, const int* in_sizes, int n_in,
                              void* d_out, int out_size) {
    (void)in_sizes; (void)n_in; (void)out_size;
    const float* x       = (const float*)d_in[0];
    const float* tin     = (const float*)d_in[1];
    const float* mask    = (const float*)d_in[2];
    const float* W_embed = (const float*)d_in[3];
    const float* b_embed = (const float*)d_in[4];
    const float* W_ih    = (const float*)d_in[5];
    const float* b_ih    = (const float*)d_in[6];
    const float* W_hh    = (const float*)d_in[7];
    const float* b_hh    = (const float*)d_in[8];
    const float* W_he    = (const float*)d_in[9];
    const float* b_he    = (const float*)d_in[10];
    const float* W_mu    = (const float*)d_in[11];
    const float* b_mu    = (const float*)d_in[12];
    const float* W_lv    = (const float*)d_in[13];
    const float* b_lv    = (const float*)d_in[14];
    const float* h_inf   = (const float*)d_in[15];
    const float* t_inf   = (const float*)d_in[16];
    const float* b_int   = (const float*)d_in[17];
    float* out = (float*)d_out;

    zero_h0_kernel<<<64, 1024>>>();
    phi_kernel<<<TB / 16, 256>>>(x, W_embed, b_embed);
    xg_kernel<<<dim3(G3 / 64, TB / 64), 256>>>(W_ih, b_ih);
    for (int t = 0; t < T_STEPS - 1; ++t)
        gru_step_kernel<<<dim3(HID / 32, BATCH / 16), 256>>>(t, W_hh, b_hh);
    loss_kernel<<<(TB - BATCH) / 8, 256>>>(x, tin, mask, W_he, b_he,
                                           W_mu, b_mu, W_lv, b_lv,
                                           h_inf, t_inf, b_int);
    reduce_kernel<<<1, 256>>>(out);
}

// round 5
// speedup vs baseline: 2.8887x; 2.8887x over previous
#include <cuda_runtime.h>
#include <math.h>
#include <stdint.h>

// Problem constants (fixed shapes from reference setup_inputs)
#define T_STEPS 512
#define BATCH   128
#define MDIM    31
#define HID     512
#define EMB     256
#define SDIM    128
#define G3      (3*HID)          // 1536
#define TB      (T_STEPS*BATCH)  // 65536
#define BH      (BATCH*HID)      // 65536

#define SIGMA_MIN 0.01f
#define GAMMA     1.0f
#define LOG2PI    1.8378770664093453f

typedef unsigned long long ull;

// Scratch (device globals: no allocations allowed)
__device__ float g_phi[TB*EMB];                 //  67 MB
__device__ float g_xg [(size_t)TB*G3];          // 402 MB
__device__ float g_hs [(size_t)TB*HID];         // 134 MB  (hs[t] = h_t; hs[0]=0)
__device__ float g_loss[TB];                    // per-(t,b) loss, t>=1 written

// grid barrier state (self-resetting across launches)
__device__ unsigned          g_bar_cnt = 0;
__device__ volatile unsigned g_bar_gen = 0;

__device__ __forceinline__ float sigmoidf_(float v) {
    return 1.0f / (1.0f + expf(-v));
}

// packed fp32x2 FMA (Blackwell f32x2 pipe): d = a*b + c elementwise
__device__ __forceinline__ ull ffma2_(ull a, ull b, ull c) {
    ull d;
    asm("fma.rn.f32x2 %0, %1, %2, %3;" : "=l"(d) : "l"(a), "l"(b), "l"(c));
    return d;
}

__device__ __forceinline__ void cp_async8(uint32_t dst, const void* src) {
    asm volatile("cp.async.ca.shared.global [%0], [%1], 8;" :: "r"(dst), "l"(src));
}

// ---------------------------------------------------------------------------
// Kernel 0: zero h_0
// ---------------------------------------------------------------------------
__global__ void zero_h0_kernel() {
    int i = blockIdx.x * blockDim.x + threadIdx.x;
    if (i < BH) g_hs[i] = 0.0f;
}

// ---------------------------------------------------------------------------
// Kernel 1: phi = relu(x @ W_embed^T + b_embed)   [TB,31] -> [TB,256]
// ---------------------------------------------------------------------------
__global__ void phi_kernel(const float* __restrict__ x,
                           const float* __restrict__ W_embed,
                           const float* __restrict__ b_embed) {
    __shared__ float Ws[EMB * MDIM];
    __shared__ float Xs[16 * MDIM];

    const int tid  = threadIdx.x;      // 256 threads
    const int row0 = blockIdx.x * 16;

    for (int i = tid; i < EMB * MDIM; i += 256) Ws[i] = W_embed[i];
    for (int i = tid; i < 16 * MDIM;  i += 256) Xs[i] = x[row0 * MDIM + i];
    __syncthreads();

    const int e = tid;
    const float be = b_embed[e];
    #pragma unroll 4
    for (int r = 0; r < 16; ++r) {
        float acc = be;
        #pragma unroll
        for (int k = 0; k < MDIM; ++k)
            acc += Xs[r * MDIM + k] * Ws[e * MDIM + k];
        g_phi[(row0 + r) * EMB + e] = fmaxf(acc, 0.0f);
    }
}

// ---------------------------------------------------------------------------
// Kernel 2: x_gates = phi @ W_ih^T + b_ih   [TB,256] x [1536,256] -> [TB,1536]
// ---------------------------------------------------------------------------
__global__ void xg_kernel(const float* __restrict__ W_ih,
                          const float* __restrict__ b_ih) {
    __shared__ float As[64][17];
    __shared__ float Bs[64][17];

    const int tid = threadIdx.x;       // 256
    const int tx = tid & 15;
    const int ty = tid >> 4;
    const int n0 = blockIdx.x * 64;
    const int m0 = blockIdx.y * 64;

    float c[4][4];
    #pragma unroll
    for (int i = 0; i < 4; ++i)
        #pragma unroll
        for (int j = 0; j < 4; ++j) c[i][j] = 0.0f;

    const int lrow = tid >> 2;
    const int lcol = (tid & 3) * 4;

    for (int kc = 0; kc < EMB; kc += 16) {
        float4 av = *reinterpret_cast<const float4*>(&g_phi[(m0 + lrow) * EMB + kc + lcol]);
        float4 bv = *reinterpret_cast<const float4*>(&W_ih[(size_t)(n0 + lrow) * EMB + kc + lcol]);
        As[lrow][lcol+0] = av.x; As[lrow][lcol+1] = av.y;
        As[lrow][lcol+2] = av.z; As[lrow][lcol+3] = av.w;
        Bs[lrow][lcol+0] = bv.x; Bs[lrow][lcol+1] = bv.y;
        Bs[lrow][lcol+2] = bv.z; Bs[lrow][lcol+3] = bv.w;
        __syncthreads();

        #pragma unroll
        for (int k = 0; k < 16; ++k) {
            float a[4], b[4];
            #pragma unroll
            for (int i = 0; i < 4; ++i) a[i] = As[ty*4 + i][k];
            #pragma unroll
            for (int j = 0; j < 4; ++j) b[j] = Bs[tx*4 + j][k];
            #pragma unroll
            for (int i = 0; i < 4; ++i)
                #pragma unroll
                for (int j = 0; j < 4; ++j) c[i][j] += a[i] * b[j];
        }
        __syncthreads();
    }

    #pragma unroll
    for (int i = 0; i < 4; ++i) {
        const int m = m0 + ty*4 + i;
        const int n = n0 + tx*4;
        float4 v;
        v.x = c[i][0] + b_ih[n+0];
        v.y = c[i][1] + b_ih[n+1];
        v.z = c[i][2] + b_ih[n+2];
        v.w = c[i][3] + b_ih[n+3];
        *reinterpret_cast<float4*>(&g_xg[(size_t)m * G3 + n]) = v;
    }
}

// ---------------------------------------------------------------------------
// Kernel 3: PERSISTENT GRU. One launch runs all 511 steps.
// 128 CTAs; CTA c owns j in [4c, 4c+4) for all 3 gates; W_hh slice cached in
// smem once. Per step: stream h_t via double-buffered cp.async chunks, FFMA2
// (f32x2) inner product with even/odd-k lane split, fused gate epilogue,
// grid-wide barrier.
// Thread map (256 thr): jl = tid&3 (local j), bh = tid>>2 -> b pair {2bh,2bh+1}
// ---------------------------------------------------------------------------
#define GRU_CTAS 128
#define PADK 66        // h-row pad (floats): 8B-aligned rows, conflict-free LDS.64
#define WPAD 514       // weight-row pad (floats)
#define BK   64        // k-chunk

#define GRU_SMEM_BYTES ((12*WPAD + 2*BATCH*PADK) * 4)   // 24672 + 67584 = 92256

__device__ __forceinline__ void grid_barrier_() {
    __syncthreads();
    if (threadIdx.x == 0) {
        unsigned gen = g_bar_gen;
        if (atomicAdd(&g_bar_cnt, 1u) == GRU_CTAS - 1) {
            g_bar_cnt = 0;
            __threadfence();
            g_bar_gen = gen + 1;
        } else {
            while (g_bar_gen == gen) { __nanosleep(32); }
            __threadfence();
        }
    }
    __syncthreads();
}

__global__ __launch_bounds__(256, 1)
void gru_persistent_kernel(const float* __restrict__ W_hh,
                           const float* __restrict__ b_hh) {
    extern __shared__ float smem[];
    float* Ws  = smem;                    // [12][WPAD]
    float* Hs0 = smem + 12*WPAD;          // [BATCH][PADK]
    float* Hs1 = Hs0 + BATCH*PADK;

    const int tid = threadIdx.x;
    const int jl  = tid & 3;
    const int bh  = tid >> 2;             // 0..63
    const int b0  = 2*bh, b1 = b0 + 1;
    const int j   = blockIdx.x*4 + jl;

    // Load this CTA's W_hh slice once: rows {g*HID + j} for g=0..2, jl=0..3
    for (int i = tid; i < 12*HID; i += 256) {
        int gj = i >> 9, k = i & (HID-1);
        int g = gj >> 2;
        int jj = blockIdx.x*4 + (gj & 3);
        Ws[gj*WPAD + k] = W_hh[((size_t)(g*HID + jj))*HID + k];
    }
    const float bhr = b_hh[j];
    const float bhz = b_hh[HID + j];
    const float bhn = b_hh[2*HID + j];
    __syncthreads();

    const uint32_t s0 = (uint32_t)__cvta_generic_to_shared(Hs0);
    const uint32_t s1 = (uint32_t)__cvta_generic_to_shared(Hs1);

    // per-thread copy pattern: fixed 8B word kw, rows b = bb0 + 8*it
    const int kw  = tid & 31;             // 8B word index within 64-float chunk
    const int bb0 = tid >> 5;             // 0..7

    auto copy_chunk = [&](uint32_t sbuf, const float* hsrc, int kc) {
        const float* src = hsrc + (size_t)bb0*HID + kc + 2*kw;
        uint32_t dst = sbuf + (uint32_t)(bb0*PADK + 2*kw) * 4u;
        #pragma unroll
        for (int it = 0; it < 16; ++it) {
            cp_async8(dst, src);
            src += 8*HID;
            dst += 8*PADK*4;
        }
    };

    for (int t = 0; t < T_STEPS - 1; ++t) {
        const float* __restrict__ hsrc = g_hs + (size_t)t*BH;
        float*       __restrict__ hdst = g_hs + (size_t)(t+1)*BH;
        const float* __restrict__ xg   = g_xg + (size_t)t*BATCH*G3;

        // Prefetch epilogue operands (latency hidden by the k loop)
        const float xr0 = xg[(size_t)b0*G3 + j];
        const float xz0 = xg[(size_t)b0*G3 + HID + j];
        const float xn0 = xg[(size_t)b0*G3 + 2*HID + j];
        const float xr1 = xg[(size_t)b1*G3 + j];
        const float xz1 = xg[(size_t)b1*G3 + HID + j];
        const float xn1 = xg[(size_t)b1*G3 + 2*HID + j];
        const float hp0 = hsrc[(size_t)b0*HID + j];
        const float hp1 = hsrc[(size_t)b1*HID + j];

        copy_chunk(s0, hsrc, 0);
        asm volatile("cp.async.commit_group;");

        ull a00=0, a01=0, a02=0, a10=0, a11=0, a12=0;

        #pragma unroll 2
        for (int c = 0; c < HID/BK; ++c) {
            if (c < HID/BK - 1) {
                copy_chunk((c & 1) ? s0 : s1, hsrc, (c+1)*BK);
                asm volatile("cp.async.commit_group;");
                asm volatile("cp.async.wait_group 1;");
            } else {
                asm volatile("cp.async.wait_group 0;");
            }
            __syncthreads();

            const float* H  = (c & 1) ? Hs1 : Hs0;
            const float* Ha = H + b0*PADK;
            const float* Hb = H + b1*PADK;
            const float* W0 = Ws + (0*4 + jl)*WPAD + c*BK;
            const float* W1 = Ws + (1*4 + jl)*WPAD + c*BK;
            const float* W2 = Ws + (2*4 + jl)*WPAD + c*BK;

            #pragma unroll
            for (int k = 0; k < BK; k += 2) {
                ull ha = *reinterpret_cast<const ull*>(Ha + k);
                ull hb = *reinterpret_cast<const ull*>(Hb + k);
                ull w0 = *reinterpret_cast<const ull*>(W0 + k);
                ull w1 = *reinterpret_cast<const ull*>(W1 + k);
                ull w2 = *reinterpret_cast<const ull*>(W2 + k);
                a00 = ffma2_(ha, w0, a00);
                a01 = ffma2_(ha, w1, a01);
                a02 = ffma2_(ha, w2, a02);
                a10 = ffma2_(hb, w0, a10);
                a11 = ffma2_(hb, w1, a11);
                a12 = ffma2_(hb, w2, a12);
            }
            __syncthreads();
        }

        // Epilogue: collapse even/odd-k lanes, gates, write h_{t+1}
        union U { ull u; float2 f; } u;
        u.u = a00; const float hr0 = u.f.x + u.f.y + bhr;
        u.u = a01; const float hz0 = u.f.x + u.f.y + bhz;
        u.u = a02; const float hn0 = u.f.x + u.f.y + bhn;
        u.u = a10; const float hr1 = u.f.x + u.f.y + bhr;
        u.u = a11; const float hz1 = u.f.x + u.f.y + bhz;
        u.u = a12; const float hn1 = u.f.x + u.f.y + bhn;

        const float r0 = sigmoidf_(xr0 + hr0);
        const float z0 = sigmoidf_(xz0 + hz0);
        const float n0 = tanhf(xn0 + r0 * hn0);
        hdst[(size_t)b0*HID + j] = (1.0f - z0) * n0 + z0 * hp0;

        const float r1 = sigmoidf_(xr1 + hr1);
        const float z1 = sigmoidf_(xz1 + hz1);
        const float n1 = tanhf(xn1 + r1 * hn1);
        hdst[(size_t)b1*HID + j] = (1.0f - z1) * n1 + z1 * hp1;

        __threadfence();
        grid_barrier_();
    }
}

// ---------------------------------------------------------------------------
// Kernel 4: per-(t,b) loss for t>=1.
// ---------------------------------------------------------------------------
__global__ void loss_kernel(const float* __restrict__ x,
                            const float* __restrict__ tin,
                            const float* __restrict__ mask,
                            const float* __restrict__ W_he,
                            const float* __restrict__ b_he,
                            const float* __restrict__ W_mu,
                            const float* __restrict__ b_mu,
                            const float* __restrict__ W_lv,
                            const float* __restrict__ b_lv,
                            const float* __restrict__ h_inf,
                            const float* __restrict__ t_inf,
                            const float* __restrict__ b_int) {
    __shared__ float Hs[8][HID];
    __shared__ float Ws[SDIM][17];
    __shared__ float He[8][SDIM];
    __shared__ float red[8][32];

    const int tid    = threadIdx.x;    // 256
    const int r_base = BATCH + blockIdx.x * 8;

    for (int i = tid; i < 8 * HID; i += 256) {
        int rr = i >> 9, k = i & (HID - 1);
        Hs[rr][k] = g_hs[(size_t)(r_base + rr) * HID + k];
    }
    __syncthreads();

    const int s    = tid & 127;
    const int rgrp = tid >> 7;
    float acc[4] = {0.f, 0.f, 0.f, 0.f};

    for (int kc = 0; kc < HID; kc += 16) {
        for (int i = tid; i < SDIM * 16; i += 256) {
            int s2 = i >> 4, k = i & 15;
            Ws[s2][k] = W_he[(size_t)s2 * HID + kc + k];
        }
        __syncthreads();
        #pragma unroll
        for (int k = 0; k < 16; ++k) {
            float w = Ws[s][k];
            #pragma unroll
            for (int q = 0; q < 4; ++q)
                acc[q] += Hs[rgrp + 2*q][kc + k] * w;
        }
        __syncthreads();
    }
    {
        const float bs = b_he[s];
        #pragma unroll
        for (int q = 0; q < 4; ++q)
            He[rgrp + 2*q][s] = fmaxf(acc[q] + bs, 0.0f);
    }
    __syncthreads();

    if (tid < 8 * MDIM) {
        const int r = tid / MDIM;
        const int m = tid % MDIM;
        float mu = b_mu[m];
        float lv = b_lv[m];
        #pragma unroll 4
        for (int k = 0; k < SDIM; ++k) {
            const float he = He[r][k];
            mu += W_mu[m * SDIM + k] * he;
            lv += W_lv[m * SDIM + k] * he;
        }
        const float sigma = fmaxf(expf(0.5f * lv), SIGMA_MIN);
        const float xv = x[(size_t)(r_base + r) * MDIM + m];
        const float d = (xv - mu) / sigma;
        red[r][m] = -0.5f * d * d - logf(sigma) - 0.5f * LOG2PI;
    }
    __syncthreads();

    if (tid < 8) {
        const int r = tid;
        float marker_ll = 0.0f;
        for (int m = 0; m < MDIM; ++m) marker_ll += red[r][m];

        float past = 0.0f;
        for (int k = 0; k < SDIM; ++k) past += He[r][k] * h_inf[k];

        const float ti = t_inf[0];
        const float bi = b_int[0];
        const float tg = tin[(size_t)(r_base + r) * 2 + 1];
        const float term1 = past + ti * tg + bi;
        const float time_ll = term1 + (expf(past + bi) - expf(term1)) / ti;

        const int row = r_base + r;
        g_loss[row] = (GAMMA * (-time_ll) + (-marker_ll)) * mask[row];
    }
}

// ---------------------------------------------------------------------------
// Kernel 5: deterministic final reduction (double accumulation)
// ---------------------------------------------------------------------------
__global__ void reduce_kernel(float* __restrict__ out) {
    __shared__ double sd[256];
    const int tid = threadIdx.x;
    double sum = 0.0;
    for (int i = BATCH + tid; i < TB; i += 256) sum += (double)g_loss[i];
    sd[tid] = sum;
    __syncthreads();
    for (int off = 128; off > 0; off >>= 1) {
        if (tid < off) sd[tid] += sd[tid + off];
        __syncthreads();
    }
    if (tid == 0) out[0] = (float)sd[0];
}

// ---------------------------------------------------------------------------
extern "C" void kernel_launch(void* const* d_in, const int* in_sizes, int n_in,
                              void* d_out, int out_size) {
    (void)in_sizes; (void)n_in; (void)out_size;
    const float* x       = (const float*)d_in[0];
    const float* tin     = (const float*)d_in[1];
    const float* mask    = (const float*)d_in[2];
    const float* W_embed = (const float*)d_in[3];
    const float* b_embed = (const float*)d_in[4];
    const float* W_ih    = (const float*)d_in[5];
    const float* b_ih    = (const float*)d_in[6];
    const float* W_hh    = (const float*)d_in[7];
    const float* b_hh    = (const float*)d_in[8];
    const float* W_he    = (const float*)d_in[9];
    const float* b_he    = (const float*)d_in[10];
    const float* W_mu    = (const float*)d_in[11];
    const float* b_mu    = (const float*)d_in[12];
    const float* W_lv    = (const float*)d_in[13];
    const float* b_lv    = (const float*)d_in[14];
    const float* h_inf   = (const float*)d_in[15];
    const float* t_inf   = (const float*)d_in[16];
    const float* b_int   = (const float*)d_in[17];
    float* out = (float*)d_out;

    cudaFuncSetAttribute(gru_persistent_kernel,
                         cudaFuncAttributeMaxDynamicSharedMemorySize,
                         GRU_SMEM_BYTES);

    zero_h0_kernel<<<64, 1024>>>();
    phi_kernel<<<TB / 16, 256>>>(x, W_embed, b_embed);
    xg_kernel<<<dim3(G3 / 64, TB / 64), 256>>>(W_ih, b_ih);
    gru_persistent_kernel<<<GRU_CTAS, 256, GRU_SMEM_BYTES>>>(W_hh, b_hh);
    loss_kernel<<<(TB - BATCH) / 8, 256>>>(x, tin, mask, W_he, b_he,
                                           W_mu, b_mu, W_lv, b_lv,
                                           h_inf, t_inf, b_int);
    reduce_kernel<<<1, 256>>>(out);
}